// round 14
// baseline (speedup 1.0000x reference)
#include <cuda_runtime.h>
#include <math.h>

// Problem constants
#define BT  128                             // B*T
#define NEDGE (BT * 64 * 64)                // 524288
#define V_SZ  ((size_t)BT * 64 * 256)       // 2097152
#define E_SZ  ((size_t)NEDGE * 128)         // 67108864
#define OFF_E  (V_SZ)
#define OFF_EI (OFF_E + E_SZ)               // 69206016
#define OFF_AB (OFF_EI + (size_t)NEDGE)     // 69730304

#define NODE_BLOCKS 128                     // BT (first in grid)
#define EDGE_BLOCKS 2048                    // BT * 16 (fine-grained)

// Precomputed per-channel edge constants (all mean-centered over h so the
// LayerNorm mean folds away):
__device__ float g_base[32];         // centered (bias + vn-fold), |dir|=1 case
__device__ float g_dC[32];           // centered (self-case minus base-case)
__device__ float g_whv[32];          // wh @ wv  (v_out projection)
__device__ float g_ctab[1024 * 32];  // rows [0,575): centered Epos@W; row 600: 0
__device__ float g_rbft[2048 * 32];  // centered RBF@W sampled at dn = r/64

__device__ __forceinline__ float bfly_sum(float v) {
    #pragma unroll
    for (int o = 16; o; o >>= 1) v += __shfl_xor_sync(0xffffffffu, v, o);
    return v;
}

// ---------------------------------------------------------------------------
// Combined init, 387 blocks x 256 (PDL primary — triggers immediately):
//   blocks [0,72)    : g_ctab rows 0..574 (centered Epos @ W)
//   blocks [72,130)  : zero g_ctab rows 575..1023
//   blocks [130,386) : g_rbft rows (centered RBF @ W at dn = r/64)
//   block  386       : per-channel folds (base / dC / whv)
// ---------------------------------------------------------------------------
__global__ __launch_bounds__(256) void init_all_kernel(
    const float* __restrict__ e_wh, const float* __restrict__ e_wsw,
    const float* __restrict__ e_wsb, const float* __restrict__ e_wv)
{
    cudaTriggerProgrammaticLaunchCompletion();
    int bxx = blockIdx.x;
    int w = threadIdx.x >> 5, l = threadIdx.x & 31;

    if (bxx < 72) {
        int g = bxx * 8 + w;
        if (g >= 575) return;
        const float FR[8] = {
            1.0f, 0.31622776601683794f, 0.1f, 0.031622776601683791f,
            0.01f, 0.0031622776601683794f, 0.001f, 0.00031622776601683794f };
        float d = (float)(g - 63);
        float acc = 0.0f;
        #pragma unroll
        for (int j = 0; j < 8; j++) {
            float s, c;
            sincosf(d * FR[j], &s, &c);
            acc = fmaf(c, e_wsw[(16 + j) * 32 + l], acc);
            acc = fmaf(s, e_wsw[(24 + j) * 32 + l], acc);
        }
        g_ctab[g * 32 + l] = acc - bfly_sum(acc) * (1.0f / 32.0f);
    } else if (bxx < 130) {
        int g = 575 + (bxx - 72) * 8 + w;
        if (g < 1024) g_ctab[g * 32 + l] = 0.0f;
    } else if (bxx < 386) {
        int r = (bxx - 130) * 8 + w;
        float dn = (float)r * (1.0f / 64.0f);
        float acc = 0.0f;
        #pragma unroll
        for (int k = 0; k < 16; k++) {
            float t = (dn - (float)k * (20.0f / 15.0f)) * 0.8f;
            acc = fmaf(expf(-t * t), e_wsw[k * 32 + l], acc);
        }
        g_rbft[r * 32 + l] = acc - bfly_sum(acc) * (1.0f / 32.0f);
    } else {
        __shared__ float sbase[32], sdC[32];
        // per-channel folds: h = w, w+8, w+16, w+24; lane = inner index m
        float whm = e_wh[l];
        float vnt = sqrtf(fmaf(whm, whm, 1e-8f));
        for (int h = w; h < 32; h += 8) {
            float wsv = e_wsw[(32 + l) * 32 + h];
            float wv  = e_wv[l * 32 + h];
            float vnc   = bfly_sum(vnt * wsv);
            float selfc = bfly_sum(sqrtf(1e-8f) * wsv);
            float whv   = bfly_sum(whm * wv);
            if (l == 0) {
                sbase[h] = e_wsb[h] + vnc;
                sdC[h]   = selfc - vnc;
                g_whv[h] = whv;
            }
        }
        __syncthreads();
        if (w == 0) {
            float b = sbase[l];
            g_base[l] = b - bfly_sum(b) * (1.0f / 32.0f);
            float dd = sdC[l];
            g_dC[l]   = dd - bfly_sum(dd) * (1.0f / 32.0f);
        }
    }
}

__device__ __forceinline__ void nrm3(float& x, float& y, float& z) {
    float n = sqrtf(x * x + y * y + z * z);
    float inv = 1.0f / fmaxf(n, 1e-12f);
    x *= inv; y *= inv; z *= inv;
}

// ---------------------------------------------------------------------------
// Mega kernel (PDL secondary): blocks [0,128) = node path (launched first so
// its latency-bound body overlaps edge work); [128, 128+2048) = edge path,
// one (row, half) pair per warp for fine-grained tail packing.
// ---------------------------------------------------------------------------
__global__ __launch_bounds__(256) void mega_kernel(
    const float* __restrict__ X, const float* __restrict__ mask,
    const int* __restrict__ chain, const int* __restrict__ focus, int L,
    const float* __restrict__ n_wh,  const float* __restrict__ n_wsw,
    const float* __restrict__ n_wsb, const float* __restrict__ n_wv,
    const float* __restrict__ lnng,  const float* __restrict__ lnnb,
    const float* __restrict__ lneg,  const float* __restrict__ lneb,
    float* __restrict__ out)
{
    __shared__ __align__(16) char smraw[26624];
    int bx = blockIdx.x;
    int tid = threadIdx.x, w = tid >> 5, l = tid & 31;

    if (bx >= NODE_BLOCKS) {
        // ================= EDGE PATH (fused sort + features + GVP + LN) ====
        int ebx = bx - NODE_BLOCKS;               // 0..2047
        float* feat = (float*)smraw;              // 8*32*8 = 2048 (16B aligned)
        float* xca  = feat + 2048;                // 192
        float* msk  = xca + 192;                  // 64
        int*   foc  = (int*)(msk + 64);           // 64
        int*   chs  = foc + 64;                   // 512
        float* Drow = (float*)(chs + 512);        // 8*64
        int*   erow = (int*)(Drow + 512);         // 8*64

        int bt = ebx >> 4, sub = ebx & 15, b = bt >> 6;
        const float* Xbt = X + (size_t)bt * 768;
        for (int idx = tid; idx < 192; idx += 256)
            xca[idx] = Xbt[(idx / 3) * 12 + 3 + (idx % 3)];
        if (tid < 64) {
            msk[tid] = mask[bt * 64 + tid];
            foc[tid] = focus[bt * 64 + tid];
        }
        const int* chainB = chain + b * L;
        bool chsm = (L <= 512);
        if (chsm) for (int idx = tid; idx < L; idx += 256) chs[idx] = chainB[idx];
        __syncthreads();

        // wait for init tables (overlapped with the staging above)
        cudaGridDependencySynchronize();

        // per-lane constants
        float baseC = g_base[l];
        float dCc   = g_dC[l];
        float whv   = g_whv[l];
        float lg = lneg[l], lb = lneb[l];

        // ---- warp -> (row, half): i = sub*4 + (w>>1), t2 = w&1 ----
        int i = sub * 4 + (w >> 1);
        int t2 = w & 1;
        float xix = xca[i * 3], xiy = xca[i * 3 + 1], xiz = xca[i * 3 + 2];
        float mi = msk[i];

        int j0 = l, j1 = l + 32;
        float d0, d1, a0_, a1_;
        {
            float dx = __fadd_rn(xca[j0 * 3],     -xix);
            float dy = __fadd_rn(xca[j0 * 3 + 1], -xiy);
            float dz = __fadd_rn(xca[j0 * 3 + 2], -xiz);
            float s = __fadd_rn(__fadd_rn(__fmul_rn(dx, dx), __fmul_rn(dy, dy)), __fmul_rn(dz, dz));
            d0 = __fmul_rn(__fmul_rn(msk[j0], mi), sqrtf(__fadd_rn(s, 1e-6f)));
            dx = __fadd_rn(xca[j1 * 3],     -xix);
            dy = __fadd_rn(xca[j1 * 3 + 1], -xiy);
            dz = __fadd_rn(xca[j1 * 3 + 2], -xiz);
            s = __fadd_rn(__fadd_rn(__fmul_rn(dx, dx), __fmul_rn(dy, dy)), __fmul_rn(dz, dz));
            d1 = __fmul_rn(__fmul_rn(msk[j1], mi), sqrtf(__fadd_rn(s, 1e-6f)));
        }
        float mx = fmaxf(d0, d1);
        #pragma unroll
        for (int o = 16; o; o >>= 1) mx = fmaxf(mx, __shfl_xor_sync(0xffffffffu, mx, o));
        float dmax = mx + 1.0f;
        {
            float m20 = __fmul_rn(msk[j0], mi);
            float m21 = __fmul_rn(msk[j1], mi);
            a0_ = __fadd_rn(d0, __fmul_rn(1.0f - m20, dmax));
            a1_ = __fadd_rn(d1, __fmul_rn(1.0f - m21, dmax));
        }
        Drow[w * 64 + j0] = a0_;
        Drow[w * 64 + j1] = a1_;
        __syncwarp();
        int r0 = 0, r1 = 0;
        #pragma unroll 16
        for (int k = 0; k < 64; k++) {
            float dk = Drow[w * 64 + k];
            r0 += (int)(dk < a0_) | ((int)(dk == a0_) & (int)(k < j0));
            r1 += (int)(dk < a1_) | ((int)(dk == a1_) & (int)(k < j1));
        }
        erow[w * 64 + r0] = j0;
        erow[w * 64 + r1] = j1;
        __syncwarp();

        int nbr0 = erow[w * 64];
        int c0 = chsm ? chs[foc[nbr0]] : chainB[foc[nbr0]];
        size_t gebase = (size_t)bt * 4096 + (size_t)i * 64;
        float* frl = feat + w * 256 + l * 8;
        const float* fw = feat + w * 256;

        {
            // ---- phase 1: lane = edge, feature row + precomputed offsets ----
            int e = t2 * 32 + l;
            int nbr = erow[w * 64 + e];
            float dn = Drow[w * 64 + nbr];
            int an = foc[nbr];
            size_t ge = gebase + e;
            out[OFF_EI + ge] = (float)nbr;
            out[OFF_AB + ge] = (float)an;

            float dx = xca[nbr * 3]     - xix;
            float dy = xca[nbr * 3 + 1] - xiy;
            float dz = xca[nbr * 3 + 2] - xiz;
            float n2 = dx * dx + dy * dy + dz * dz;
            float invn = 1.0f / fmaxf(sqrtf(n2), 1e-12f);

            int same = ((chsm ? chs[an] : chainB[an]) == c0);
            float s = (n2 == 0.0f) ? 1.0f : 0.0f;
            int ctrow = same ? (an - i + 63) : 600;
            float dn64 = fminf(dn * 64.0f, 2046.9f);
            int ia = (int)dn64;
            float fa = dn64 - (float)ia;
            {
                float4 v = {dx * invn, dy * invn, dz * invn, s};
                *reinterpret_cast<float4*>(frl) = v;
                float4 u = {__int_as_float(ctrow * 32), __int_as_float(ia * 32), fa, 0.0f};
                *reinterpret_cast<float4*>(frl + 4) = u;
            }
            __syncwarp();

            // ---- phase 2: lane = channel, 2-edge interleaved, LN-centered ----
            float* po = out + (OFF_E + (gebase + (size_t)(t2 * 32)) * 128) + l;
            for (int t = 0; t < 32; t += 2) {
                const float4* p = (const float4*)(fw + t * 8);
                float4 A0 = p[0], B0 = p[1];
                float4 A1 = p[2], B1 = p[3];
                int co0 = __float_as_int(B0.x), ro0 = __float_as_int(B0.y);
                int co1 = __float_as_int(B1.x), ro1 = __float_as_int(B1.y);
                float ct0 = g_ctab[co0 + l];
                float ct1 = g_ctab[co1 + l];
                float r00 = g_rbft[ro0 + l], r01 = g_rbft[ro0 + 32 + l];
                float r10 = g_rbft[ro1 + l], r11 = g_rbft[ro1 + 32 + l];
                float dv0 = fmaf(B0.z, r01 - r00, r00 + ct0);
                float dv1 = fmaf(B1.z, r11 - r10, r10 + ct1);
                dv0 += fmaf(A0.w, dCc, baseC);
                dv1 += fmaf(A1.w, dCc, baseC);

                // single variance butterfly per edge (2-way interleaved)
                float q0 = dv0 * dv0, q1 = dv1 * dv1;
                #pragma unroll
                for (int o = 16; o; o >>= 1) {
                    q0 += __shfl_xor_sync(0xffffffffu, q0, o);
                    q1 += __shfl_xor_sync(0xffffffffu, q1, o);
                }
                float iv0 = rsqrtf(fmaf(q0, 1.0f / 32.0f, 1e-5f));
                float iv1 = rsqrtf(fmaf(q1, 1.0f / 32.0f, 1e-5f));
                float so0 = fmaf(dv0 * iv0, lg, lb);
                float so1 = fmaf(dv1 * iv1, lg, lb);

                po[0]   = A0.x * whv;
                po[32]  = A0.y * whv;
                po[64]  = A0.z * whv;
                po[96]  = so0;
                po[128] = A1.x * whv;
                po[160] = A1.y * whv;
                po[192] = A1.z * whv;
                po[224] = so1;
                po += 256;
            }
        }
    } else {
        // ========================= NODE PATH (no init dependency) ==========
        float* wsw  = (float*)smraw;          // 70*64
        float* whs  = wsw + 4480;             // 3*64
        float* whvs = whs + 192;              // 3*64
        float* wsb  = whvs + 192;             // 64
        float* glng = wsb + 64;               // 64
        float* glnb = glng + 64;              // 64
        float* sdi  = glnb + 64;              // 64*6
        float* vmat = sdi + 384;              // 64*9
        float* vnbuf = vmat + 576;            // 8*64 (16B aligned)

        int bt = bx;

        for (int idx = tid; idx < 4480; idx += 256) wsw[idx] = n_wsw[idx];
        for (int idx = tid; idx < 192; idx += 256)  whs[idx] = n_wh[idx];
        if (tid < 64) { wsb[tid] = n_wsb[tid]; glng[tid] = lnng[tid]; glnb[tid] = lnnb[tid]; }

        const float* Xbt = X + (size_t)bt * 768;
        if (tid < 192) {
            // dihedrals: one (i,t) per thread
            int i = tid / 3, t = tid - 3 * i;
            int r = 3 * i + t - 1;
            float ang = 0.0f;
            if (r >= 0 && r < 189) {
                float P[4][3];
                #pragma unroll
                for (int qq = 0; qq < 4; qq++) {
                    int p = r + qq;
                    const float* A = Xbt + (p / 3) * 12 + (p % 3) * 3;
                    P[qq][0] = A[0]; P[qq][1] = A[1]; P[qq][2] = A[2];
                }
                float u2x = P[1][0] - P[0][0], u2y = P[1][1] - P[0][1], u2z = P[1][2] - P[0][2];
                float u1x = P[2][0] - P[1][0], u1y = P[2][1] - P[1][1], u1z = P[2][2] - P[1][2];
                float u0x = P[3][0] - P[2][0], u0y = P[3][1] - P[2][1], u0z = P[3][2] - P[2][2];
                nrm3(u2x, u2y, u2z); nrm3(u1x, u1y, u1z); nrm3(u0x, u0y, u0z);
                float ax = u2y * u1z - u2z * u1y;
                float ay = u2z * u1x - u2x * u1z;
                float az = u2x * u1y - u2y * u1x; nrm3(ax, ay, az);
                float bx_ = u1y * u0z - u1z * u0y;
                float by_ = u1z * u0x - u1x * u0z;
                float bz_ = u1x * u0y - u1y * u0x; nrm3(bx_, by_, bz_);
                float cd = ax * bx_ + ay * by_ + az * bz_;
                cd = fminf(fmaxf(cd, -1.0f + 1e-7f), 1.0f - 1e-7f);
                float sg = u2x * bx_ + u2y * by_ + u2z * bz_;
                float sn = (sg > 0.f) ? 1.f : ((sg < 0.f) ? -1.f : 0.f);
                ang = sn * acosf(cd);
            }
            sdi[i * 6 + t]     = cosf(ang);
            sdi[i * 6 + 3 + t] = sinf(ang);
        } else {
            // frames: sidechain vec + fwd + bwd, one node per thread
            int i = tid - 192;
            const float* Xr = Xbt + (size_t)i * 12;
            float nx = Xr[0], ny = Xr[1], nz = Xr[2];
            float ox = Xr[3], oy = Xr[4], oz = Xr[5];
            float cx = Xr[6], cy = Xr[7], cz = Xr[8];
            float ccx = cx - ox, ccy = cy - oy, ccz = cz - oz; nrm3(ccx, ccy, ccz);
            float nnx = nx - ox, nny = ny - oy, nnz = nz - oz; nrm3(nnx, nny, nnz);
            float bxv = ccx + nnx, byv = ccy + nny, bzv = ccz + nnz; nrm3(bxv, byv, bzv);
            float px = ccy * nnz - ccz * nny;
            float py = ccz * nnx - ccx * nnz;
            float pz = ccx * nny - ccy * nnx; nrm3(px, py, pz);
            const float k1 = 0.57735026918962576f, k2 = 0.81649658092772603f;
            vmat[i * 9 + 0] = -bxv * k1 - px * k2;
            vmat[i * 9 + 3] = -byv * k1 - py * k2;
            vmat[i * 9 + 6] = -bzv * k1 - pz * k2;
            float fx = 0.f, fy = 0.f, fz = 0.f;
            if (i < 63) {
                const float* Xn2 = Xbt + (size_t)(i + 1) * 12 + 3;
                fx = Xn2[0] - ox; fy = Xn2[1] - oy; fz = Xn2[2] - oz; nrm3(fx, fy, fz);
            }
            vmat[i * 9 + 1] = fx; vmat[i * 9 + 4] = fy; vmat[i * 9 + 7] = fz;
            float gx = 0.f, gy = 0.f, gz = 0.f;
            if (i > 0) {
                const float* Xp = Xbt + (size_t)(i - 1) * 12 + 3;
                gx = ox - Xp[0]; gy = oy - Xp[1]; gz = oz - Xp[2]; nrm3(gx, gy, gz);
                gx = -gx; gy = -gy; gz = -gz;
            }
            vmat[i * 9 + 2] = gx; vmat[i * 9 + 5] = gy; vmat[i * 9 + 8] = gz;
        }
        __syncthreads();

        // whv = wh @ wv (3 x 64)
        for (int idx = tid; idx < 192; idx += 256) {
            int p = idx >> 6, h = idx & 63;
            float a = 0.f;
            for (int m = 0; m < 64; m++) a = fmaf(whs[p * 64 + m], n_wv[m * 64 + h], a);
            whvs[idx] = a;
        }
        __syncthreads();

        for (int nd = w; nd < 64; nd += 8) {
            float vm[9];
            #pragma unroll
            for (int z = 0; z < 9; z++) vm[z] = vmat[nd * 9 + z];
            int h0 = l, h1 = l + 32;
            float vh0[3], vh1[3];
            #pragma unroll
            for (int c = 0; c < 3; c++) {
                vh0[c] = vm[c * 3 + 0] * whs[0 * 64 + h0] + vm[c * 3 + 1] * whs[1 * 64 + h0] + vm[c * 3 + 2] * whs[2 * 64 + h0];
                vh1[c] = vm[c * 3 + 0] * whs[0 * 64 + h1] + vm[c * 3 + 1] * whs[1 * 64 + h1] + vm[c * 3 + 2] * whs[2 * 64 + h1];
            }
            float vn0 = sqrtf(vh0[0] * vh0[0] + vh0[1] * vh0[1] + vh0[2] * vh0[2] + 1e-8f);
            float vn1 = sqrtf(vh1[0] * vh1[0] + vh1[1] * vh1[1] + vh1[2] * vh1[2] + 1e-8f);
            vnbuf[w * 64 + l] = vn0;
            vnbuf[w * 64 + l + 32] = vn1;
            __syncwarp();

            float acc0 = wsb[h0], acc1 = wsb[h1];
            #pragma unroll
            for (int k = 0; k < 6; k++) {
                float dk = sdi[nd * 6 + k];
                acc0 = fmaf(dk, wsw[k * 64 + h0], acc0);
                acc1 = fmaf(dk, wsw[k * 64 + h1], acc1);
            }
            #pragma unroll
            for (int m = 0; m < 64; m += 4) {
                float4 v4 = *reinterpret_cast<const float4*>(&vnbuf[w * 64 + m]);
                acc0 = fmaf(v4.x, wsw[(6 + m) * 64 + h0], acc0);
                acc1 = fmaf(v4.x, wsw[(6 + m) * 64 + h1], acc1);
                acc0 = fmaf(v4.y, wsw[(7 + m) * 64 + h0], acc0);
                acc1 = fmaf(v4.y, wsw[(7 + m) * 64 + h1], acc1);
                acc0 = fmaf(v4.z, wsw[(8 + m) * 64 + h0], acc0);
                acc1 = fmaf(v4.z, wsw[(8 + m) * 64 + h1], acc1);
                acc0 = fmaf(v4.w, wsw[(9 + m) * 64 + h0], acc0);
                acc1 = fmaf(v4.w, wsw[(9 + m) * 64 + h1], acc1);
            }
            __syncwarp();

            // LayerNorm over 64 channels: 2 interleaved butterflies
            float ssum = acc0 + acc1;
            #pragma unroll
            for (int o = 16; o; o >>= 1) ssum += __shfl_xor_sync(0xffffffffu, ssum, o);
            float mean = ssum * (1.0f / 64.0f);
            float dv0 = acc0 - mean, dv1 = acc1 - mean;
            float vs = dv0 * dv0 + dv1 * dv1;
            #pragma unroll
            for (int o = 16; o; o >>= 1) vs += __shfl_xor_sync(0xffffffffu, vs, o);
            float inv = rsqrtf(vs * (1.0f / 64.0f) + 1e-5f);
            float o0 = dv0 * inv * glng[h0] + glnb[h0];
            float o1 = dv1 * inv * glng[h1] + glnb[h1];

            size_t vb = ((size_t)bt * 64 + nd) * 256;
            #pragma unroll
            for (int c = 0; c < 3; c++) {
                float vo0 = vm[c * 3 + 0] * whvs[0 * 64 + h0] + vm[c * 3 + 1] * whvs[1 * 64 + h0] + vm[c * 3 + 2] * whvs[2 * 64 + h0];
                float vo1 = vm[c * 3 + 0] * whvs[0 * 64 + h1] + vm[c * 3 + 1] * whvs[1 * 64 + h1] + vm[c * 3 + 2] * whvs[2 * 64 + h1];
                out[vb + c * 64 + h0] = vo0;
                out[vb + c * 64 + h1] = vo1;
            }
            out[vb + 192 + h0] = o0;
            out[vb + 192 + h1] = o1;
        }
    }
}

// ---------------------------------------------------------------------------
extern "C" void kernel_launch(void* const* d_in, const int* in_sizes, int n_in,
                              void* d_out, int out_size)
{
    const float* X      = (const float*)d_in[0];
    const float* mask   = (const float*)d_in[1];
    const int*   chain  = (const int*)d_in[2];
    const int*   focus  = (const int*)d_in[3];
    const float* n_wh   = (const float*)d_in[4];
    const float* n_wsw  = (const float*)d_in[5];
    const float* n_wsb  = (const float*)d_in[6];
    const float* n_wv   = (const float*)d_in[7];
    const float* e_wh   = (const float*)d_in[8];
    const float* e_wsw  = (const float*)d_in[9];
    const float* e_wsb  = (const float*)d_in[10];
    const float* e_wv   = (const float*)d_in[11];
    const float* ln_n_g = (const float*)d_in[12];
    const float* ln_n_b = (const float*)d_in[13];
    const float* ln_e_g = (const float*)d_in[14];
    const float* ln_e_b = (const float*)d_in[15];
    float* out = (float*)d_out;
    int L = in_sizes[2] / 2;

    init_all_kernel<<<387, 256>>>(e_wh, e_wsw, e_wsb, e_wv);

    // PDL secondary: launch mega so its prologue overlaps init.
    cudaLaunchConfig_t cfg = {};
    cfg.gridDim = dim3(NODE_BLOCKS + EDGE_BLOCKS, 1, 1);
    cfg.blockDim = dim3(256, 1, 1);
    cfg.dynamicSmemBytes = 0;
    cfg.stream = 0;
    cudaLaunchAttribute attrs[1];
    attrs[0].id = cudaLaunchAttributeProgrammaticStreamSerialization;
    attrs[0].val.programmaticStreamSerializationAllowed = 1;
    cfg.attrs = attrs;
    cfg.numAttrs = 1;
    cudaLaunchKernelEx(&cfg, mega_kernel,
        X, mask, chain, focus, L,
        n_wh, n_wsw, n_wsb, n_wv,
        ln_n_g, ln_n_b, ln_e_g, ln_e_b, out);
}

// round 15
// speedup vs baseline: 1.2298x; 1.2298x over previous
#include <cuda_runtime.h>
#include <math.h>

// Problem constants
#define BT  128                             // B*T
#define NEDGE (BT * 64 * 64)                // 524288
#define V_SZ  ((size_t)BT * 64 * 256)       // 2097152
#define E_SZ  ((size_t)NEDGE * 128)         // 67108864
#define OFF_E  (V_SZ)
#define OFF_EI (OFF_E + E_SZ)               // 69206016
#define OFF_AB (OFF_EI + (size_t)NEDGE)     // 69730304

#define NODE_BLOCKS 128                     // BT (first in grid)
#define EDGE_BLOCKS 2048                    // BT * 16 (fine-grained)

// Precomputed per-channel edge constants (all mean-centered over h so the
// LayerNorm mean folds away):
__device__ float g_base[32];         // centered (bias + vn-fold), |dir|=1 case
__device__ float g_dC[32];           // centered (self-case minus base-case)
__device__ float g_whv[32];          // wh @ wv  (v_out projection)
__device__ float g_ctab[1024 * 32];  // rows [0,575): centered Epos@W; row 600: 0
__device__ float g_rbft[2048 * 32];  // centered RBF@W sampled at dn = r/64

__device__ __forceinline__ float bfly_sum(float v) {
    #pragma unroll
    for (int o = 16; o; o >>= 1) v += __shfl_xor_sync(0xffffffffu, v, o);
    return v;
}

// ---------------------------------------------------------------------------
// Combined init, 387 blocks x 256 (PDL primary — triggers immediately):
//   blocks [0,72)    : g_ctab rows 0..574 (centered Epos @ W)
//   blocks [72,130)  : zero g_ctab rows 575..1023
//   blocks [130,386) : g_rbft rows (centered RBF @ W at dn = r/64)
//   block  386       : per-channel folds (base / dC / whv)
// ---------------------------------------------------------------------------
__global__ __launch_bounds__(256) void init_all_kernel(
    const float* __restrict__ e_wh, const float* __restrict__ e_wsw,
    const float* __restrict__ e_wsb, const float* __restrict__ e_wv)
{
    cudaTriggerProgrammaticLaunchCompletion();
    int bxx = blockIdx.x;
    int w = threadIdx.x >> 5, l = threadIdx.x & 31;

    if (bxx < 72) {
        int g = bxx * 8 + w;
        if (g >= 575) return;
        const float FR[8] = {
            1.0f, 0.31622776601683794f, 0.1f, 0.031622776601683791f,
            0.01f, 0.0031622776601683794f, 0.001f, 0.00031622776601683794f };
        float d = (float)(g - 63);
        float acc = 0.0f;
        #pragma unroll
        for (int j = 0; j < 8; j++) {
            float s, c;
            sincosf(d * FR[j], &s, &c);
            acc = fmaf(c, e_wsw[(16 + j) * 32 + l], acc);
            acc = fmaf(s, e_wsw[(24 + j) * 32 + l], acc);
        }
        g_ctab[g * 32 + l] = acc - bfly_sum(acc) * (1.0f / 32.0f);
    } else if (bxx < 130) {
        int g = 575 + (bxx - 72) * 8 + w;
        if (g < 1024) g_ctab[g * 32 + l] = 0.0f;
    } else if (bxx < 386) {
        int r = (bxx - 130) * 8 + w;
        float dn = (float)r * (1.0f / 64.0f);
        float acc = 0.0f;
        #pragma unroll
        for (int k = 0; k < 16; k++) {
            float t = (dn - (float)k * (20.0f / 15.0f)) * 0.8f;
            acc = fmaf(expf(-t * t), e_wsw[k * 32 + l], acc);
        }
        g_rbft[r * 32 + l] = acc - bfly_sum(acc) * (1.0f / 32.0f);
    } else {
        __shared__ float sbase[32], sdC[32];
        // per-channel folds: h = w, w+8, w+16, w+24; lane = inner index m
        float whm = e_wh[l];
        float vnt = sqrtf(fmaf(whm, whm, 1e-8f));
        for (int h = w; h < 32; h += 8) {
            float wsv = e_wsw[(32 + l) * 32 + h];
            float wv  = e_wv[l * 32 + h];
            float vnc   = bfly_sum(vnt * wsv);
            float selfc = bfly_sum(sqrtf(1e-8f) * wsv);
            float whv   = bfly_sum(whm * wv);
            if (l == 0) {
                sbase[h] = e_wsb[h] + vnc;
                sdC[h]   = selfc - vnc;
                g_whv[h] = whv;
            }
        }
        __syncthreads();
        if (w == 0) {
            float b = sbase[l];
            g_base[l] = b - bfly_sum(b) * (1.0f / 32.0f);
            float dd = sdC[l];
            g_dC[l]   = dd - bfly_sum(dd) * (1.0f / 32.0f);
        }
    }
}

__device__ __forceinline__ void nrm3(float& x, float& y, float& z) {
    float n = sqrtf(x * x + y * y + z * z);
    float inv = 1.0f / fmaxf(n, 1e-12f);
    x *= inv; y *= inv; z *= inv;
}

// ---------------------------------------------------------------------------
// Mega kernel (PDL secondary): blocks [0,128) = node path (first, latency-
// bound body overlaps edge work); [128, 128+2048) = edge path, one (row,half)
// per warp. Static smem padded to 32KB to cap residency at 7 blocks/SM,
// leaving one SM slot free so init blocks co-schedule under PDL.
// ---------------------------------------------------------------------------
__global__ __launch_bounds__(256) void mega_kernel(
    const float* __restrict__ X, const float* __restrict__ mask,
    const int* __restrict__ chain, const int* __restrict__ focus, int L,
    const float* __restrict__ n_wh,  const float* __restrict__ n_wsw,
    const float* __restrict__ n_wsb, const float* __restrict__ n_wv,
    const float* __restrict__ lnng,  const float* __restrict__ lnnb,
    const float* __restrict__ lneg,  const float* __restrict__ lneb,
    float* __restrict__ out)
{
    __shared__ __align__(16) char smraw[32768];   // padded: 7 blocks/SM cap
    int bx = blockIdx.x;
    int tid = threadIdx.x, w = tid >> 5, l = tid & 31;

    if (bx >= NODE_BLOCKS) {
        // ================= EDGE PATH (fused sort + features + GVP + LN) ====
        int ebx = bx - NODE_BLOCKS;               // 0..2047
        float* feat = (float*)smraw;              // 8*32*8 = 2048 (16B aligned)
        float* xca  = feat + 2048;                // 192
        float* msk  = xca + 192;                  // 64
        int*   foc  = (int*)(msk + 64);           // 64
        int*   chs  = foc + 64;                   // 512
        float* Drow = (float*)(chs + 512);        // 8*64
        int*   erow = (int*)(Drow + 512);         // 8*64

        int bt = ebx >> 4, sub = ebx & 15, b = bt >> 6;
        const float* Xbt = X + (size_t)bt * 768;
        for (int idx = tid; idx < 192; idx += 256)
            xca[idx] = Xbt[(idx / 3) * 12 + 3 + (idx % 3)];
        if (tid < 64) {
            msk[tid] = mask[bt * 64 + tid];
            foc[tid] = focus[bt * 64 + tid];
        }
        const int* chainB = chain + b * L;
        bool chsm = (L <= 512);
        if (chsm) for (int idx = tid; idx < L; idx += 256) chs[idx] = chainB[idx];
        __syncthreads();

        // wait for init tables (overlapped with the staging above)
        cudaGridDependencySynchronize();

        // per-lane constants
        float baseC = g_base[l];
        float dCc   = g_dC[l];
        float whv   = g_whv[l];
        float lg = lneg[l], lb = lneb[l];

        // ---- warp -> (row, half): i = sub*4 + (w>>1), t2 = w&1 ----
        int i = sub * 4 + (w >> 1);
        int t2 = w & 1;
        float xix = xca[i * 3], xiy = xca[i * 3 + 1], xiz = xca[i * 3 + 2];
        float mi = msk[i];

        int j0 = l, j1 = l + 32;
        float d0, d1, a0_, a1_;
        {
            float dx = __fadd_rn(xca[j0 * 3],     -xix);
            float dy = __fadd_rn(xca[j0 * 3 + 1], -xiy);
            float dz = __fadd_rn(xca[j0 * 3 + 2], -xiz);
            float s = __fadd_rn(__fadd_rn(__fmul_rn(dx, dx), __fmul_rn(dy, dy)), __fmul_rn(dz, dz));
            d0 = __fmul_rn(__fmul_rn(msk[j0], mi), sqrtf(__fadd_rn(s, 1e-6f)));
            dx = __fadd_rn(xca[j1 * 3],     -xix);
            dy = __fadd_rn(xca[j1 * 3 + 1], -xiy);
            dz = __fadd_rn(xca[j1 * 3 + 2], -xiz);
            s = __fadd_rn(__fadd_rn(__fmul_rn(dx, dx), __fmul_rn(dy, dy)), __fmul_rn(dz, dz));
            d1 = __fmul_rn(__fmul_rn(msk[j1], mi), sqrtf(__fadd_rn(s, 1e-6f)));
        }
        float mx = fmaxf(d0, d1);
        #pragma unroll
        for (int o = 16; o; o >>= 1) mx = fmaxf(mx, __shfl_xor_sync(0xffffffffu, mx, o));
        float dmax = mx + 1.0f;
        {
            float m20 = __fmul_rn(msk[j0], mi);
            float m21 = __fmul_rn(msk[j1], mi);
            a0_ = __fadd_rn(d0, __fmul_rn(1.0f - m20, dmax));
            a1_ = __fadd_rn(d1, __fmul_rn(1.0f - m21, dmax));
        }
        Drow[w * 64 + j0] = a0_;
        Drow[w * 64 + j1] = a1_;
        __syncwarp();
        int r0 = 0, r1 = 0;
        #pragma unroll 16
        for (int k = 0; k < 64; k++) {
            float dk = Drow[w * 64 + k];
            r0 += (int)(dk < a0_) | ((int)(dk == a0_) & (int)(k < j0));
            r1 += (int)(dk < a1_) | ((int)(dk == a1_) & (int)(k < j1));
        }
        erow[w * 64 + r0] = j0;
        erow[w * 64 + r1] = j1;
        __syncwarp();

        int nbr0 = erow[w * 64];
        int c0 = chsm ? chs[foc[nbr0]] : chainB[foc[nbr0]];
        size_t gebase = (size_t)bt * 4096 + (size_t)i * 64;
        float* frl = feat + w * 256 + l * 8;
        const float* fw = feat + w * 256;

        {
            // ---- phase 1: lane = edge, feature row + precomputed offsets ----
            int e = t2 * 32 + l;
            int nbr = erow[w * 64 + e];
            float dn = Drow[w * 64 + nbr];
            int an = foc[nbr];
            size_t ge = gebase + e;
            out[OFF_EI + ge] = (float)nbr;
            out[OFF_AB + ge] = (float)an;

            float dx = xca[nbr * 3]     - xix;
            float dy = xca[nbr * 3 + 1] - xiy;
            float dz = xca[nbr * 3 + 2] - xiz;
            float n2 = dx * dx + dy * dy + dz * dz;
            float invn = 1.0f / fmaxf(sqrtf(n2), 1e-12f);

            int same = ((chsm ? chs[an] : chainB[an]) == c0);
            float s = (n2 == 0.0f) ? 1.0f : 0.0f;
            int ctrow = same ? (an - i + 63) : 600;
            float dn64 = fminf(dn * 64.0f, 2046.9f);
            int ia = (int)dn64;
            float fa = dn64 - (float)ia;
            {
                float4 v = {dx * invn, dy * invn, dz * invn, s};
                *reinterpret_cast<float4*>(frl) = v;
                float4 u = {__int_as_float(ctrow * 32), __int_as_float(ia * 32), fa, 0.0f};
                *reinterpret_cast<float4*>(frl + 4) = u;
            }
            __syncwarp();

            // ---- phase 2: lane = channel, 2-edge interleaved, LN-centered ----
            float* po = out + (OFF_E + (gebase + (size_t)(t2 * 32)) * 128) + l;
            for (int t = 0; t < 32; t += 2) {
                const float4* p = (const float4*)(fw + t * 8);
                float4 A0 = p[0], B0 = p[1];
                float4 A1 = p[2], B1 = p[3];
                int co0 = __float_as_int(B0.x), ro0 = __float_as_int(B0.y);
                int co1 = __float_as_int(B1.x), ro1 = __float_as_int(B1.y);
                float ct0 = g_ctab[co0 + l];
                float ct1 = g_ctab[co1 + l];
                float r00 = g_rbft[ro0 + l], r01 = g_rbft[ro0 + 32 + l];
                float r10 = g_rbft[ro1 + l], r11 = g_rbft[ro1 + 32 + l];
                float dv0 = fmaf(B0.z, r01 - r00, r00 + ct0);
                float dv1 = fmaf(B1.z, r11 - r10, r10 + ct1);
                dv0 += fmaf(A0.w, dCc, baseC);
                dv1 += fmaf(A1.w, dCc, baseC);

                // single variance butterfly per edge (2-way interleaved)
                float q0 = dv0 * dv0, q1 = dv1 * dv1;
                #pragma unroll
                for (int o = 16; o; o >>= 1) {
                    q0 += __shfl_xor_sync(0xffffffffu, q0, o);
                    q1 += __shfl_xor_sync(0xffffffffu, q1, o);
                }
                float iv0 = rsqrtf(fmaf(q0, 1.0f / 32.0f, 1e-5f));
                float iv1 = rsqrtf(fmaf(q1, 1.0f / 32.0f, 1e-5f));
                float so0 = fmaf(dv0 * iv0, lg, lb);
                float so1 = fmaf(dv1 * iv1, lg, lb);

                po[0]   = A0.x * whv;
                po[32]  = A0.y * whv;
                po[64]  = A0.z * whv;
                po[96]  = so0;
                po[128] = A1.x * whv;
                po[160] = A1.y * whv;
                po[192] = A1.z * whv;
                po[224] = so1;
                po += 256;
            }
        }
    } else {
        // ========================= NODE PATH (no init dependency) ==========
        float* wsw  = (float*)smraw;          // 70*64
        float* whs  = wsw + 4480;             // 3*64
        float* whvs = whs + 192;              // 3*64
        float* wsb  = whvs + 192;             // 64
        float* glng = wsb + 64;               // 64
        float* glnb = glng + 64;              // 64
        float* sdi  = glnb + 64;              // 64*6
        float* vmat = sdi + 384;              // 64*9
        float* vnbuf = vmat + 576;            // 8*64 (16B aligned)

        int bt = bx;

        for (int idx = tid; idx < 4480; idx += 256) wsw[idx] = n_wsw[idx];
        for (int idx = tid; idx < 192; idx += 256)  whs[idx] = n_wh[idx];
        if (tid < 64) { wsb[tid] = n_wsb[tid]; glng[tid] = lnng[tid]; glnb[tid] = lnnb[tid]; }

        const float* Xbt = X + (size_t)bt * 768;
        if (tid < 192) {
            // dihedrals: one (i,t) per thread
            int i = tid / 3, t = tid - 3 * i;
            int r = 3 * i + t - 1;
            float ang = 0.0f;
            if (r >= 0 && r < 189) {
                float P[4][3];
                #pragma unroll
                for (int qq = 0; qq < 4; qq++) {
                    int p = r + qq;
                    const float* A = Xbt + (p / 3) * 12 + (p % 3) * 3;
                    P[qq][0] = A[0]; P[qq][1] = A[1]; P[qq][2] = A[2];
                }
                float u2x = P[1][0] - P[0][0], u2y = P[1][1] - P[0][1], u2z = P[1][2] - P[0][2];
                float u1x = P[2][0] - P[1][0], u1y = P[2][1] - P[1][1], u1z = P[2][2] - P[1][2];
                float u0x = P[3][0] - P[2][0], u0y = P[3][1] - P[2][1], u0z = P[3][2] - P[2][2];
                nrm3(u2x, u2y, u2z); nrm3(u1x, u1y, u1z); nrm3(u0x, u0y, u0z);
                float ax = u2y * u1z - u2z * u1y;
                float ay = u2z * u1x - u2x * u1z;
                float az = u2x * u1y - u2y * u1x; nrm3(ax, ay, az);
                float bx_ = u1y * u0z - u1z * u0y;
                float by_ = u1z * u0x - u1x * u0z;
                float bz_ = u1x * u0y - u1y * u0x; nrm3(bx_, by_, bz_);
                float cd = ax * bx_ + ay * by_ + az * bz_;
                cd = fminf(fmaxf(cd, -1.0f + 1e-7f), 1.0f - 1e-7f);
                float sg = u2x * bx_ + u2y * by_ + u2z * bz_;
                float sn = (sg > 0.f) ? 1.f : ((sg < 0.f) ? -1.f : 0.f);
                ang = sn * acosf(cd);
            }
            sdi[i * 6 + t]     = cosf(ang);
            sdi[i * 6 + 3 + t] = sinf(ang);
        } else {
            // frames: sidechain vec + fwd + bwd, one node per thread
            int i = tid - 192;
            const float* Xr = Xbt + (size_t)i * 12;
            float nx = Xr[0], ny = Xr[1], nz = Xr[2];
            float ox = Xr[3], oy = Xr[4], oz = Xr[5];
            float cx = Xr[6], cy = Xr[7], cz = Xr[8];
            float ccx = cx - ox, ccy = cy - oy, ccz = cz - oz; nrm3(ccx, ccy, ccz);
            float nnx = nx - ox, nny = ny - oy, nnz = nz - oz; nrm3(nnx, nny, nnz);
            float bxv = ccx + nnx, byv = ccy + nny, bzv = ccz + nnz; nrm3(bxv, byv, bzv);
            float px = ccy * nnz - ccz * nny;
            float py = ccz * nnx - ccx * nnz;
            float pz = ccx * nny - ccy * nnx; nrm3(px, py, pz);
            const float k1 = 0.57735026918962576f, k2 = 0.81649658092772603f;
            vmat[i * 9 + 0] = -bxv * k1 - px * k2;
            vmat[i * 9 + 3] = -byv * k1 - py * k2;
            vmat[i * 9 + 6] = -bzv * k1 - pz * k2;
            float fx = 0.f, fy = 0.f, fz = 0.f;
            if (i < 63) {
                const float* Xn2 = Xbt + (size_t)(i + 1) * 12 + 3;
                fx = Xn2[0] - ox; fy = Xn2[1] - oy; fz = Xn2[2] - oz; nrm3(fx, fy, fz);
            }
            vmat[i * 9 + 1] = fx; vmat[i * 9 + 4] = fy; vmat[i * 9 + 7] = fz;
            float gx = 0.f, gy = 0.f, gz = 0.f;
            if (i > 0) {
                const float* Xp = Xbt + (size_t)(i - 1) * 12 + 3;
                gx = ox - Xp[0]; gy = oy - Xp[1]; gz = oz - Xp[2]; nrm3(gx, gy, gz);
                gx = -gx; gy = -gy; gz = -gz;
            }
            vmat[i * 9 + 2] = gx; vmat[i * 9 + 5] = gy; vmat[i * 9 + 8] = gz;
        }
        __syncthreads();

        // whv = wh @ wv (3 x 64)
        for (int idx = tid; idx < 192; idx += 256) {
            int p = idx >> 6, h = idx & 63;
            float a = 0.f;
            for (int m = 0; m < 64; m++) a = fmaf(whs[p * 64 + m], n_wv[m * 64 + h], a);
            whvs[idx] = a;
        }
        __syncthreads();

        for (int nd = w; nd < 64; nd += 8) {
            float vm[9];
            #pragma unroll
            for (int z = 0; z < 9; z++) vm[z] = vmat[nd * 9 + z];
            int h0 = l, h1 = l + 32;
            float vh0[3], vh1[3];
            #pragma unroll
            for (int c = 0; c < 3; c++) {
                vh0[c] = vm[c * 3 + 0] * whs[0 * 64 + h0] + vm[c * 3 + 1] * whs[1 * 64 + h0] + vm[c * 3 + 2] * whs[2 * 64 + h0];
                vh1[c] = vm[c * 3 + 0] * whs[0 * 64 + h1] + vm[c * 3 + 1] * whs[1 * 64 + h1] + vm[c * 3 + 2] * whs[2 * 64 + h1];
            }
            float vn0 = sqrtf(vh0[0] * vh0[0] + vh0[1] * vh0[1] + vh0[2] * vh0[2] + 1e-8f);
            float vn1 = sqrtf(vh1[0] * vh1[0] + vh1[1] * vh1[1] + vh1[2] * vh1[2] + 1e-8f);
            vnbuf[w * 64 + l] = vn0;
            vnbuf[w * 64 + l + 32] = vn1;
            __syncwarp();

            float acc0 = wsb[h0], acc1 = wsb[h1];
            #pragma unroll
            for (int k = 0; k < 6; k++) {
                float dk = sdi[nd * 6 + k];
                acc0 = fmaf(dk, wsw[k * 64 + h0], acc0);
                acc1 = fmaf(dk, wsw[k * 64 + h1], acc1);
            }
            #pragma unroll
            for (int m = 0; m < 64; m += 4) {
                float4 v4 = *reinterpret_cast<const float4*>(&vnbuf[w * 64 + m]);
                acc0 = fmaf(v4.x, wsw[(6 + m) * 64 + h0], acc0);
                acc1 = fmaf(v4.x, wsw[(6 + m) * 64 + h1], acc1);
                acc0 = fmaf(v4.y, wsw[(7 + m) * 64 + h0], acc0);
                acc1 = fmaf(v4.y, wsw[(7 + m) * 64 + h1], acc1);
                acc0 = fmaf(v4.z, wsw[(8 + m) * 64 + h0], acc0);
                acc1 = fmaf(v4.z, wsw[(8 + m) * 64 + h1], acc1);
                acc0 = fmaf(v4.w, wsw[(9 + m) * 64 + h0], acc0);
                acc1 = fmaf(v4.w, wsw[(9 + m) * 64 + h1], acc1);
            }
            __syncwarp();

            // LayerNorm over 64 channels: 2 interleaved butterflies
            float ssum = acc0 + acc1;
            #pragma unroll
            for (int o = 16; o; o >>= 1) ssum += __shfl_xor_sync(0xffffffffu, ssum, o);
            float mean = ssum * (1.0f / 64.0f);
            float dv0 = acc0 - mean, dv1 = acc1 - mean;
            float vs = dv0 * dv0 + dv1 * dv1;
            #pragma unroll
            for (int o = 16; o; o >>= 1) vs += __shfl_xor_sync(0xffffffffu, vs, o);
            float inv = rsqrtf(vs * (1.0f / 64.0f) + 1e-5f);
            float o0 = dv0 * inv * glng[h0] + glnb[h0];
            float o1 = dv1 * inv * glng[h1] + glnb[h1];

            size_t vb = ((size_t)bt * 64 + nd) * 256;
            #pragma unroll
            for (int c = 0; c < 3; c++) {
                float vo0 = vm[c * 3 + 0] * whvs[0 * 64 + h0] + vm[c * 3 + 1] * whvs[1 * 64 + h0] + vm[c * 3 + 2] * whvs[2 * 64 + h0];
                float vo1 = vm[c * 3 + 0] * whvs[0 * 64 + h1] + vm[c * 3 + 1] * whvs[1 * 64 + h1] + vm[c * 3 + 2] * whvs[2 * 64 + h1];
                out[vb + c * 64 + h0] = vo0;
                out[vb + c * 64 + h1] = vo1;
            }
            out[vb + 192 + h0] = o0;
            out[vb + 192 + h1] = o1;
        }
    }
}

// ---------------------------------------------------------------------------
extern "C" void kernel_launch(void* const* d_in, const int* in_sizes, int n_in,
                              void* d_out, int out_size)
{
    const float* X      = (const float*)d_in[0];
    const float* mask   = (const float*)d_in[1];
    const int*   chain  = (const int*)d_in[2];
    const int*   focus  = (const int*)d_in[3];
    const float* n_wh   = (const float*)d_in[4];
    const float* n_wsw  = (const float*)d_in[5];
    const float* n_wsb  = (const float*)d_in[6];
    const float* n_wv   = (const float*)d_in[7];
    const float* e_wh   = (const float*)d_in[8];
    const float* e_wsw  = (const float*)d_in[9];
    const float* e_wsb  = (const float*)d_in[10];
    const float* e_wv   = (const float*)d_in[11];
    const float* ln_n_g = (const float*)d_in[12];
    const float* ln_n_b = (const float*)d_in[13];
    const float* ln_e_g = (const float*)d_in[14];
    const float* ln_e_b = (const float*)d_in[15];
    float* out = (float*)d_out;
    int L = in_sizes[2] / 2;

    init_all_kernel<<<387, 256>>>(e_wh, e_wsw, e_wsb, e_wv);

    // PDL secondary: launch mega so its prologue overlaps init.
    cudaLaunchConfig_t cfg = {};
    cfg.gridDim = dim3(NODE_BLOCKS + EDGE_BLOCKS, 1, 1);
    cfg.blockDim = dim3(256, 1, 1);
    cfg.dynamicSmemBytes = 0;
    cfg.stream = 0;
    cudaLaunchAttribute attrs[1];
    attrs[0].id = cudaLaunchAttributeProgrammaticStreamSerialization;
    attrs[0].val.programmaticStreamSerializationAllowed = 1;
    cfg.attrs = attrs;
    cfg.numAttrs = 1;
    cudaLaunchKernelEx(&cfg, mega_kernel,
        X, mask, chain, focus, L,
        n_wh, n_wsw, n_wsb, n_wv,
        ln_n_g, ln_n_b, ln_e_g, ln_e_b, out);
}

// round 16
// speedup vs baseline: 1.2304x; 1.0004x over previous
#include <cuda_runtime.h>
#include <math.h>

// Problem constants
#define BT  128                             // B*T
#define NEDGE (BT * 64 * 64)                // 524288
#define V_SZ  ((size_t)BT * 64 * 256)       // 2097152
#define E_SZ  ((size_t)NEDGE * 128)         // 67108864
#define OFF_E  (V_SZ)
#define OFF_EI (OFF_E + E_SZ)               // 69206016
#define OFF_AB (OFF_EI + (size_t)NEDGE)     // 69730304

#define NODE_BLOCKS 128                     // BT (first in grid)
#define EDGE_BLOCKS 2048                    // BT * 16 (fine-grained)

// Precomputed per-channel edge constants (all mean-centered over h so the
// LayerNorm mean folds away):
__device__ float g_base[32];         // centered (bias + vn-fold), |dir|=1 case
__device__ float g_dC[32];           // centered (self-case minus base-case)
__device__ float g_whv[32];          // wh @ wv  (v_out projection)
__device__ float g_ctab[1024 * 32];  // rows [0,575): centered Epos@W; row 600: 0
__device__ float g_rbft[2048 * 32];  // centered RBF@W sampled at dn = r/64

__device__ __forceinline__ float bfly_sum(float v) {
    #pragma unroll
    for (int o = 16; o; o >>= 1) v += __shfl_xor_sync(0xffffffffu, v, o);
    return v;
}

// ---------------------------------------------------------------------------
// Combined init, 387 blocks x 256 (PDL primary — triggers immediately):
//   blocks [0,72)    : g_ctab rows 0..574 (centered Epos @ W)
//   blocks [72,130)  : zero g_ctab rows 575..1023
//   blocks [130,386) : g_rbft rows (centered RBF @ W at dn = r/64)
//   block  386       : per-channel folds (base / dC / whv)
// ---------------------------------------------------------------------------
__global__ __launch_bounds__(256) void init_all_kernel(
    const float* __restrict__ e_wh, const float* __restrict__ e_wsw,
    const float* __restrict__ e_wsb, const float* __restrict__ e_wv)
{
    cudaTriggerProgrammaticLaunchCompletion();
    int bxx = blockIdx.x;
    int w = threadIdx.x >> 5, l = threadIdx.x & 31;

    if (bxx < 72) {
        int g = bxx * 8 + w;
        if (g >= 575) return;
        const float FR[8] = {
            1.0f, 0.31622776601683794f, 0.1f, 0.031622776601683791f,
            0.01f, 0.0031622776601683794f, 0.001f, 0.00031622776601683794f };
        float d = (float)(g - 63);
        float acc = 0.0f;
        #pragma unroll
        for (int j = 0; j < 8; j++) {
            float s, c;
            sincosf(d * FR[j], &s, &c);
            acc = fmaf(c, e_wsw[(16 + j) * 32 + l], acc);
            acc = fmaf(s, e_wsw[(24 + j) * 32 + l], acc);
        }
        g_ctab[g * 32 + l] = acc - bfly_sum(acc) * (1.0f / 32.0f);
    } else if (bxx < 130) {
        int g = 575 + (bxx - 72) * 8 + w;
        if (g < 1024) g_ctab[g * 32 + l] = 0.0f;
    } else if (bxx < 386) {
        int r = (bxx - 130) * 8 + w;
        float dn = (float)r * (1.0f / 64.0f);
        float acc = 0.0f;
        #pragma unroll
        for (int k = 0; k < 16; k++) {
            float t = (dn - (float)k * (20.0f / 15.0f)) * 0.8f;
            acc = fmaf(expf(-t * t), e_wsw[k * 32 + l], acc);
        }
        g_rbft[r * 32 + l] = acc - bfly_sum(acc) * (1.0f / 32.0f);
    } else {
        __shared__ float sbase[32], sdC[32];
        // per-channel folds: h = w, w+8, w+16, w+24; lane = inner index m
        float whm = e_wh[l];
        float vnt = sqrtf(fmaf(whm, whm, 1e-8f));
        for (int h = w; h < 32; h += 8) {
            float wsv = e_wsw[(32 + l) * 32 + h];
            float wv  = e_wv[l * 32 + h];
            float vnc   = bfly_sum(vnt * wsv);
            float selfc = bfly_sum(sqrtf(1e-8f) * wsv);
            float whv   = bfly_sum(whm * wv);
            if (l == 0) {
                sbase[h] = e_wsb[h] + vnc;
                sdC[h]   = selfc - vnc;
                g_whv[h] = whv;
            }
        }
        __syncthreads();
        if (w == 0) {
            float b = sbase[l];
            g_base[l] = b - bfly_sum(b) * (1.0f / 32.0f);
            float dd = sdC[l];
            g_dC[l]   = dd - bfly_sum(dd) * (1.0f / 32.0f);
        }
    }
}

__device__ __forceinline__ void nrm3(float& x, float& y, float& z) {
    float n = sqrtf(x * x + y * y + z * z);
    float inv = 1.0f / fmaxf(n, 1e-12f);
    x *= inv; y *= inv; z *= inv;
}

// ---------------------------------------------------------------------------
// Mega kernel (PDL secondary): blocks [0,128) = node path (first, latency-
// bound body overlaps edge work); [128, 128+2048) = edge path. Warps 2r,2r+1
// share row r: even warp computes the sort once, barrier publishes it.
// Static smem padded to 32KB so init blocks co-schedule under PDL.
// ---------------------------------------------------------------------------
__global__ __launch_bounds__(256) void mega_kernel(
    const float* __restrict__ X, const float* __restrict__ mask,
    const int* __restrict__ chain, const int* __restrict__ focus, int L,
    const float* __restrict__ n_wh,  const float* __restrict__ n_wsw,
    const float* __restrict__ n_wsb, const float* __restrict__ n_wv,
    const float* __restrict__ lnng,  const float* __restrict__ lnnb,
    const float* __restrict__ lneg,  const float* __restrict__ lneb,
    float* __restrict__ out)
{
    __shared__ __align__(16) char smraw[32768];   // padded: residency cap
    int bx = blockIdx.x;
    int tid = threadIdx.x, w = tid >> 5, l = tid & 31;

    if (bx >= NODE_BLOCKS) {
        // ================= EDGE PATH (fused sort + features + GVP + LN) ====
        int ebx = bx - NODE_BLOCKS;               // 0..2047
        float* feat = (float*)smraw;              // 8*32*8 = 2048 (16B aligned)
        float* xca  = feat + 2048;                // 192
        float* msk  = xca + 192;                  // 64
        int*   foc  = (int*)(msk + 64);           // 64
        int*   chs  = foc + 64;                   // 512
        float* Drow = (float*)(chs + 512);        // 4*64 (shared per row)
        int*   erow = (int*)(Drow + 256);         // 4*64

        int bt = ebx >> 4, sub = ebx & 15, b = bt >> 6;
        const float* Xbt = X + (size_t)bt * 768;
        for (int idx = tid; idx < 192; idx += 256)
            xca[idx] = Xbt[(idx / 3) * 12 + 3 + (idx % 3)];
        if (tid < 64) {
            msk[tid] = mask[bt * 64 + tid];
            foc[tid] = focus[bt * 64 + tid];
        }
        const int* chainB = chain + b * L;
        bool chsm = (L <= 512);
        if (chsm) for (int idx = tid; idx < L; idx += 256) chs[idx] = chainB[idx];
        __syncthreads();

        // wait for init tables (overlapped with the staging above)
        cudaGridDependencySynchronize();

        // per-lane constants
        float baseC = g_base[l];
        float dCc   = g_dC[l];
        float whv   = g_whv[l];
        float lg = lneg[l], lb = lneb[l];

        // ---- warp -> (row, half): r = w>>1, t2 = w&1; even warp sorts ----
        int r = w >> 1;
        int i = sub * 4 + r;
        int t2 = w & 1;
        float xix = xca[i * 3], xiy = xca[i * 3 + 1], xiz = xca[i * 3 + 2];
        float mi = msk[i];

        if (t2 == 0) {
            int j0 = l, j1 = l + 32;
            float d0, d1, a0_, a1_;
            {
                float dx = __fadd_rn(xca[j0 * 3],     -xix);
                float dy = __fadd_rn(xca[j0 * 3 + 1], -xiy);
                float dz = __fadd_rn(xca[j0 * 3 + 2], -xiz);
                float s = __fadd_rn(__fadd_rn(__fmul_rn(dx, dx), __fmul_rn(dy, dy)), __fmul_rn(dz, dz));
                d0 = __fmul_rn(__fmul_rn(msk[j0], mi), sqrtf(__fadd_rn(s, 1e-6f)));
                dx = __fadd_rn(xca[j1 * 3],     -xix);
                dy = __fadd_rn(xca[j1 * 3 + 1], -xiy);
                dz = __fadd_rn(xca[j1 * 3 + 2], -xiz);
                s = __fadd_rn(__fadd_rn(__fmul_rn(dx, dx), __fmul_rn(dy, dy)), __fmul_rn(dz, dz));
                d1 = __fmul_rn(__fmul_rn(msk[j1], mi), sqrtf(__fadd_rn(s, 1e-6f)));
            }
            float mx = fmaxf(d0, d1);
            #pragma unroll
            for (int o = 16; o; o >>= 1) mx = fmaxf(mx, __shfl_xor_sync(0xffffffffu, mx, o));
            float dmax = mx + 1.0f;
            {
                float m20 = __fmul_rn(msk[j0], mi);
                float m21 = __fmul_rn(msk[j1], mi);
                a0_ = __fadd_rn(d0, __fmul_rn(1.0f - m20, dmax));
                a1_ = __fadd_rn(d1, __fmul_rn(1.0f - m21, dmax));
            }
            Drow[r * 64 + j0] = a0_;
            Drow[r * 64 + j1] = a1_;
            __syncwarp();
            int r0 = 0, r1 = 0;
            #pragma unroll 16
            for (int k = 0; k < 64; k++) {
                float dk = Drow[r * 64 + k];
                r0 += (int)(dk < a0_) | ((int)(dk == a0_) & (int)(k < j0));
                r1 += (int)(dk < a1_) | ((int)(dk == a1_) & (int)(k < j1));
            }
            erow[r * 64 + r0] = j0;
            erow[r * 64 + r1] = j1;
        }
        __syncthreads();

        int nbr0 = erow[r * 64];
        int c0 = chsm ? chs[foc[nbr0]] : chainB[foc[nbr0]];
        size_t gebase = (size_t)bt * 4096 + (size_t)i * 64;
        float* frl = feat + w * 256 + l * 8;
        const float* fw = feat + w * 256;

        {
            // ---- phase 1: lane = edge, feature row + precomputed offsets ----
            int e = t2 * 32 + l;
            int nbr = erow[r * 64 + e];
            float dn = Drow[r * 64 + nbr];
            int an = foc[nbr];
            size_t ge = gebase + e;
            out[OFF_EI + ge] = (float)nbr;
            out[OFF_AB + ge] = (float)an;

            float dx = xca[nbr * 3]     - xix;
            float dy = xca[nbr * 3 + 1] - xiy;
            float dz = xca[nbr * 3 + 2] - xiz;
            float n2 = dx * dx + dy * dy + dz * dz;
            float invn = 1.0f / fmaxf(sqrtf(n2), 1e-12f);

            int same = ((chsm ? chs[an] : chainB[an]) == c0);
            float s = (n2 == 0.0f) ? 1.0f : 0.0f;
            int ctrow = same ? (an - i + 63) : 600;
            float dn64 = fminf(dn * 64.0f, 2046.9f);
            int ia = (int)dn64;
            float fa = dn64 - (float)ia;
            {
                float4 v = {dx * invn, dy * invn, dz * invn, s};
                *reinterpret_cast<float4*>(frl) = v;
                float4 u = {__int_as_float(ctrow * 32), __int_as_float(ia * 32), fa, 0.0f};
                *reinterpret_cast<float4*>(frl + 4) = u;
            }
            __syncwarp();

            // ---- phase 2: lane = channel, 2-edge interleaved, LN-centered ----
            float* po = out + (OFF_E + (gebase + (size_t)(t2 * 32)) * 128) + l;
            for (int t = 0; t < 32; t += 2) {
                const float4* p = (const float4*)(fw + t * 8);
                float4 A0 = p[0], B0 = p[1];
                float4 A1 = p[2], B1 = p[3];
                int co0 = __float_as_int(B0.x), ro0 = __float_as_int(B0.y);
                int co1 = __float_as_int(B1.x), ro1 = __float_as_int(B1.y);
                float ct0 = g_ctab[co0 + l];
                float ct1 = g_ctab[co1 + l];
                float r00 = g_rbft[ro0 + l], r01 = g_rbft[ro0 + 32 + l];
                float r10 = g_rbft[ro1 + l], r11 = g_rbft[ro1 + 32 + l];
                float dv0 = fmaf(B0.z, r01 - r00, r00 + ct0);
                float dv1 = fmaf(B1.z, r11 - r10, r10 + ct1);
                dv0 += fmaf(A0.w, dCc, baseC);
                dv1 += fmaf(A1.w, dCc, baseC);

                // single variance butterfly per edge (2-way interleaved)
                float q0 = dv0 * dv0, q1 = dv1 * dv1;
                #pragma unroll
                for (int o = 16; o; o >>= 1) {
                    q0 += __shfl_xor_sync(0xffffffffu, q0, o);
                    q1 += __shfl_xor_sync(0xffffffffu, q1, o);
                }
                float iv0 = rsqrtf(fmaf(q0, 1.0f / 32.0f, 1e-5f));
                float iv1 = rsqrtf(fmaf(q1, 1.0f / 32.0f, 1e-5f));
                float so0 = fmaf(dv0 * iv0, lg, lb);
                float so1 = fmaf(dv1 * iv1, lg, lb);

                po[0]   = A0.x * whv;
                po[32]  = A0.y * whv;
                po[64]  = A0.z * whv;
                po[96]  = so0;
                po[128] = A1.x * whv;
                po[160] = A1.y * whv;
                po[192] = A1.z * whv;
                po[224] = so1;
                po += 256;
            }
        }
    } else {
        // ========================= NODE PATH (no init dependency) ==========
        float* wsw  = (float*)smraw;          // 70*64
        float* whs  = wsw + 4480;             // 3*64
        float* whvs = whs + 192;              // 3*64
        float* wsb  = whvs + 192;             // 64
        float* glng = wsb + 64;               // 64
        float* glnb = glng + 64;              // 64
        float* sdi  = glnb + 64;              // 64*6
        float* vmat = sdi + 384;              // 64*9
        float* vnbuf = vmat + 576;            // 8*64 (16B aligned)

        int bt = bx;

        for (int idx = tid; idx < 4480; idx += 256) wsw[idx] = n_wsw[idx];
        for (int idx = tid; idx < 192; idx += 256)  whs[idx] = n_wh[idx];
        if (tid < 64) { wsb[tid] = n_wsb[tid]; glng[tid] = lnng[tid]; glnb[tid] = lnnb[tid]; }

        const float* Xbt = X + (size_t)bt * 768;
        if (tid < 192) {
            // dihedrals: one (i,t) per thread
            int i = tid / 3, t = tid - 3 * i;
            int r = 3 * i + t - 1;
            float ang = 0.0f;
            if (r >= 0 && r < 189) {
                float P[4][3];
                #pragma unroll
                for (int qq = 0; qq < 4; qq++) {
                    int p = r + qq;
                    const float* A = Xbt + (p / 3) * 12 + (p % 3) * 3;
                    P[qq][0] = A[0]; P[qq][1] = A[1]; P[qq][2] = A[2];
                }
                float u2x = P[1][0] - P[0][0], u2y = P[1][1] - P[0][1], u2z = P[1][2] - P[0][2];
                float u1x = P[2][0] - P[1][0], u1y = P[2][1] - P[1][1], u1z = P[2][2] - P[1][2];
                float u0x = P[3][0] - P[2][0], u0y = P[3][1] - P[2][1], u0z = P[3][2] - P[2][2];
                nrm3(u2x, u2y, u2z); nrm3(u1x, u1y, u1z); nrm3(u0x, u0y, u0z);
                float ax = u2y * u1z - u2z * u1y;
                float ay = u2z * u1x - u2x * u1z;
                float az = u2x * u1y - u2y * u1x; nrm3(ax, ay, az);
                float bx_ = u1y * u0z - u1z * u0y;
                float by_ = u1z * u0x - u1x * u0z;
                float bz_ = u1x * u0y - u1y * u0x; nrm3(bx_, by_, bz_);
                float cd = ax * bx_ + ay * by_ + az * bz_;
                cd = fminf(fmaxf(cd, -1.0f + 1e-7f), 1.0f - 1e-7f);
                float sg = u2x * bx_ + u2y * by_ + u2z * bz_;
                float sn = (sg > 0.f) ? 1.f : ((sg < 0.f) ? -1.f : 0.f);
                ang = sn * acosf(cd);
            }
            sdi[i * 6 + t]     = cosf(ang);
            sdi[i * 6 + 3 + t] = sinf(ang);
        } else {
            // frames: sidechain vec + fwd + bwd, one node per thread
            int i = tid - 192;
            const float* Xr = Xbt + (size_t)i * 12;
            float nx = Xr[0], ny = Xr[1], nz = Xr[2];
            float ox = Xr[3], oy = Xr[4], oz = Xr[5];
            float cx = Xr[6], cy = Xr[7], cz = Xr[8];
            float ccx = cx - ox, ccy = cy - oy, ccz = cz - oz; nrm3(ccx, ccy, ccz);
            float nnx = nx - ox, nny = ny - oy, nnz = nz - oz; nrm3(nnx, nny, nnz);
            float bxv = ccx + nnx, byv = ccy + nny, bzv = ccz + nnz; nrm3(bxv, byv, bzv);
            float px = ccy * nnz - ccz * nny;
            float py = ccz * nnx - ccx * nnz;
            float pz = ccx * nny - ccy * nnx; nrm3(px, py, pz);
            const float k1 = 0.57735026918962576f, k2 = 0.81649658092772603f;
            vmat[i * 9 + 0] = -bxv * k1 - px * k2;
            vmat[i * 9 + 3] = -byv * k1 - py * k2;
            vmat[i * 9 + 6] = -bzv * k1 - pz * k2;
            float fx = 0.f, fy = 0.f, fz = 0.f;
            if (i < 63) {
                const float* Xn2 = Xbt + (size_t)(i + 1) * 12 + 3;
                fx = Xn2[0] - ox; fy = Xn2[1] - oy; fz = Xn2[2] - oz; nrm3(fx, fy, fz);
            }
            vmat[i * 9 + 1] = fx; vmat[i * 9 + 4] = fy; vmat[i * 9 + 7] = fz;
            float gx = 0.f, gy = 0.f, gz = 0.f;
            if (i > 0) {
                const float* Xp = Xbt + (size_t)(i - 1) * 12 + 3;
                gx = ox - Xp[0]; gy = oy - Xp[1]; gz = oz - Xp[2]; nrm3(gx, gy, gz);
                gx = -gx; gy = -gy; gz = -gz;
            }
            vmat[i * 9 + 2] = gx; vmat[i * 9 + 5] = gy; vmat[i * 9 + 8] = gz;
        }
        __syncthreads();

        // whv = wh @ wv (3 x 64)
        for (int idx = tid; idx < 192; idx += 256) {
            int p = idx >> 6, h = idx & 63;
            float a = 0.f;
            for (int m = 0; m < 64; m++) a = fmaf(whs[p * 64 + m], n_wv[m * 64 + h], a);
            whvs[idx] = a;
        }
        __syncthreads();

        for (int nd = w; nd < 64; nd += 8) {
            float vm[9];
            #pragma unroll
            for (int z = 0; z < 9; z++) vm[z] = vmat[nd * 9 + z];
            int h0 = l, h1 = l + 32;
            float vh0[3], vh1[3];
            #pragma unroll
            for (int c = 0; c < 3; c++) {
                vh0[c] = vm[c * 3 + 0] * whs[0 * 64 + h0] + vm[c * 3 + 1] * whs[1 * 64 + h0] + vm[c * 3 + 2] * whs[2 * 64 + h0];
                vh1[c] = vm[c * 3 + 0] * whs[0 * 64 + h1] + vm[c * 3 + 1] * whs[1 * 64 + h1] + vm[c * 3 + 2] * whs[2 * 64 + h1];
            }
            float vn0 = sqrtf(vh0[0] * vh0[0] + vh0[1] * vh0[1] + vh0[2] * vh0[2] + 1e-8f);
            float vn1 = sqrtf(vh1[0] * vh1[0] + vh1[1] * vh1[1] + vh1[2] * vh1[2] + 1e-8f);
            vnbuf[w * 64 + l] = vn0;
            vnbuf[w * 64 + l + 32] = vn1;
            __syncwarp();

            float acc0 = wsb[h0], acc1 = wsb[h1];
            #pragma unroll
            for (int k = 0; k < 6; k++) {
                float dk = sdi[nd * 6 + k];
                acc0 = fmaf(dk, wsw[k * 64 + h0], acc0);
                acc1 = fmaf(dk, wsw[k * 64 + h1], acc1);
            }
            #pragma unroll
            for (int m = 0; m < 64; m += 4) {
                float4 v4 = *reinterpret_cast<const float4*>(&vnbuf[w * 64 + m]);
                acc0 = fmaf(v4.x, wsw[(6 + m) * 64 + h0], acc0);
                acc1 = fmaf(v4.x, wsw[(6 + m) * 64 + h1], acc1);
                acc0 = fmaf(v4.y, wsw[(7 + m) * 64 + h0], acc0);
                acc1 = fmaf(v4.y, wsw[(7 + m) * 64 + h1], acc1);
                acc0 = fmaf(v4.z, wsw[(8 + m) * 64 + h0], acc0);
                acc1 = fmaf(v4.z, wsw[(8 + m) * 64 + h1], acc1);
                acc0 = fmaf(v4.w, wsw[(9 + m) * 64 + h0], acc0);
                acc1 = fmaf(v4.w, wsw[(9 + m) * 64 + h1], acc1);
            }
            __syncwarp();

            // LayerNorm over 64 channels: 2 interleaved butterflies
            float ssum = acc0 + acc1;
            #pragma unroll
            for (int o = 16; o; o >>= 1) ssum += __shfl_xor_sync(0xffffffffu, ssum, o);
            float mean = ssum * (1.0f / 64.0f);
            float dv0 = acc0 - mean, dv1 = acc1 - mean;
            float vs = dv0 * dv0 + dv1 * dv1;
            #pragma unroll
            for (int o = 16; o; o >>= 1) vs += __shfl_xor_sync(0xffffffffu, vs, o);
            float inv = rsqrtf(vs * (1.0f / 64.0f) + 1e-5f);
            float o0 = dv0 * inv * glng[h0] + glnb[h0];
            float o1 = dv1 * inv * glng[h1] + glnb[h1];

            size_t vb = ((size_t)bt * 64 + nd) * 256;
            #pragma unroll
            for (int c = 0; c < 3; c++) {
                float vo0 = vm[c * 3 + 0] * whvs[0 * 64 + h0] + vm[c * 3 + 1] * whvs[1 * 64 + h0] + vm[c * 3 + 2] * whvs[2 * 64 + h0];
                float vo1 = vm[c * 3 + 0] * whvs[0 * 64 + h1] + vm[c * 3 + 1] * whvs[1 * 64 + h1] + vm[c * 3 + 2] * whvs[2 * 64 + h1];
                out[vb + c * 64 + h0] = vo0;
                out[vb + c * 64 + h1] = vo1;
            }
            out[vb + 192 + h0] = o0;
            out[vb + 192 + h1] = o1;
        }
    }
}

// ---------------------------------------------------------------------------
extern "C" void kernel_launch(void* const* d_in, const int* in_sizes, int n_in,
                              void* d_out, int out_size)
{
    const float* X      = (const float*)d_in[0];
    const float* mask   = (const float*)d_in[1];
    const int*   chain  = (const int*)d_in[2];
    const int*   focus  = (const int*)d_in[3];
    const float* n_wh   = (const float*)d_in[4];
    const float* n_wsw  = (const float*)d_in[5];
    const float* n_wsb  = (const float*)d_in[6];
    const float* n_wv   = (const float*)d_in[7];
    const float* e_wh   = (const float*)d_in[8];
    const float* e_wsw  = (const float*)d_in[9];
    const float* e_wsb  = (const float*)d_in[10];
    const float* e_wv   = (const float*)d_in[11];
    const float* ln_n_g = (const float*)d_in[12];
    const float* ln_n_b = (const float*)d_in[13];
    const float* ln_e_g = (const float*)d_in[14];
    const float* ln_e_b = (const float*)d_in[15];
    float* out = (float*)d_out;
    int L = in_sizes[2] / 2;

    init_all_kernel<<<387, 256>>>(e_wh, e_wsw, e_wsb, e_wv);

    // PDL secondary: launch mega so its prologue overlaps init.
    cudaLaunchConfig_t cfg = {};
    cfg.gridDim = dim3(NODE_BLOCKS + EDGE_BLOCKS, 1, 1);
    cfg.blockDim = dim3(256, 1, 1);
    cfg.dynamicSmemBytes = 0;
    cfg.stream = 0;
    cudaLaunchAttribute attrs[1];
    attrs[0].id = cudaLaunchAttributeProgrammaticStreamSerialization;
    attrs[0].val.programmaticStreamSerializationAllowed = 1;
    cfg.attrs = attrs;
    cfg.numAttrs = 1;
    cudaLaunchKernelEx(&cfg, mega_kernel,
        X, mask, chain, focus, L,
        n_wh, n_wsw, n_wsb, n_wv,
        ln_n_g, ln_n_b, ln_e_g, ln_e_b, out);
}

// round 17
// speedup vs baseline: 1.2665x; 1.0294x over previous
#include <cuda_runtime.h>
#include <math.h>

// Problem constants
#define BT  128                             // B*T
#define NEDGE (BT * 64 * 64)                // 524288
#define V_SZ  ((size_t)BT * 64 * 256)       // 2097152
#define E_SZ  ((size_t)NEDGE * 128)         // 67108864
#define OFF_E  (V_SZ)
#define OFF_EI (OFF_E + E_SZ)               // 69206016
#define OFF_AB (OFF_EI + (size_t)NEDGE)     // 69730304

#define NODE_BLOCKS 128                     // BT (first in grid)
#define EDGE_BLOCKS 2048                    // BT * 16 (fine-grained)

// Precomputed per-channel edge constants (all mean-centered over h so the
// LayerNorm mean folds away):
__device__ float g_base[32];         // centered (bias + vn-fold), |dir|=1 case
__device__ float g_dC[32];           // centered (self-case minus base-case)
__device__ float g_whv[32];          // wh @ wv  (v_out projection)
__device__ float g_ctab[1024 * 32];  // rows [0,575): centered Epos@W; row 600: 0
__device__ float g_rbft[2048 * 32];  // centered RBF@W sampled at dn = r/64

__device__ __forceinline__ float bfly_sum(float v) {
    #pragma unroll
    for (int o = 16; o; o >>= 1) v += __shfl_xor_sync(0xffffffffu, v, o);
    return v;
}

// ---------------------------------------------------------------------------
// Combined init, 387 blocks x 256 (PDL primary — triggers immediately):
//   blocks [0,72)    : g_ctab rows 0..574 (centered Epos @ W)
//   blocks [72,130)  : zero g_ctab rows 575..1023
//   blocks [130,386) : g_rbft rows (centered RBF @ W at dn = r/64)
//   block  386       : per-channel folds (base / dC / whv)
// ---------------------------------------------------------------------------
__global__ __launch_bounds__(256) void init_all_kernel(
    const float* __restrict__ e_wh, const float* __restrict__ e_wsw,
    const float* __restrict__ e_wsb, const float* __restrict__ e_wv)
{
    cudaTriggerProgrammaticLaunchCompletion();
    int bxx = blockIdx.x;
    int w = threadIdx.x >> 5, l = threadIdx.x & 31;

    if (bxx < 72) {
        int g = bxx * 8 + w;
        if (g >= 575) return;
        const float FR[8] = {
            1.0f, 0.31622776601683794f, 0.1f, 0.031622776601683791f,
            0.01f, 0.0031622776601683794f, 0.001f, 0.00031622776601683794f };
        float d = (float)(g - 63);
        float acc = 0.0f;
        #pragma unroll
        for (int j = 0; j < 8; j++) {
            float s, c;
            sincosf(d * FR[j], &s, &c);
            acc = fmaf(c, e_wsw[(16 + j) * 32 + l], acc);
            acc = fmaf(s, e_wsw[(24 + j) * 32 + l], acc);
        }
        g_ctab[g * 32 + l] = acc - bfly_sum(acc) * (1.0f / 32.0f);
    } else if (bxx < 130) {
        int g = 575 + (bxx - 72) * 8 + w;
        if (g < 1024) g_ctab[g * 32 + l] = 0.0f;
    } else if (bxx < 386) {
        int r = (bxx - 130) * 8 + w;
        float dn = (float)r * (1.0f / 64.0f);
        float acc = 0.0f;
        #pragma unroll
        for (int k = 0; k < 16; k++) {
            float t = (dn - (float)k * (20.0f / 15.0f)) * 0.8f;
            acc = fmaf(expf(-t * t), e_wsw[k * 32 + l], acc);
        }
        g_rbft[r * 32 + l] = acc - bfly_sum(acc) * (1.0f / 32.0f);
    } else {
        __shared__ float sbase[32], sdC[32];
        // per-channel folds: h = w, w+8, w+16, w+24; lane = inner index m
        float whm = e_wh[l];
        float vnt = sqrtf(fmaf(whm, whm, 1e-8f));
        for (int h = w; h < 32; h += 8) {
            float wsv = e_wsw[(32 + l) * 32 + h];
            float wv  = e_wv[l * 32 + h];
            float vnc   = bfly_sum(vnt * wsv);
            float selfc = bfly_sum(sqrtf(1e-8f) * wsv);
            float whv   = bfly_sum(whm * wv);
            if (l == 0) {
                sbase[h] = e_wsb[h] + vnc;
                sdC[h]   = selfc - vnc;
                g_whv[h] = whv;
            }
        }
        __syncthreads();
        if (w == 0) {
            float b = sbase[l];
            g_base[l] = b - bfly_sum(b) * (1.0f / 32.0f);
            float dd = sdC[l];
            g_dC[l]   = dd - bfly_sum(dd) * (1.0f / 32.0f);
        }
    }
}

__device__ __forceinline__ void nrm3(float& x, float& y, float& z) {
    float n = sqrtf(x * x + y * y + z * z);
    float inv = 1.0f / fmaxf(n, 1e-12f);
    x *= inv; y *= inv; z *= inv;
}

// ---------------------------------------------------------------------------
// Mega kernel (PDL secondary): blocks [0,128) = node path (first, latency-
// bound body overlaps edge work); [128, 128+2048) = edge path. Warps 2r,2r+1
// share row r (even warp sorts once). The grid-dependency sync is deferred
// until AFTER phase 1 — staging, sort, feature build, and EI/AB stores need
// no init table, so they overlap init's execution.
// ---------------------------------------------------------------------------
__global__ __launch_bounds__(256) void mega_kernel(
    const float* __restrict__ X, const float* __restrict__ mask,
    const int* __restrict__ chain, const int* __restrict__ focus, int L,
    const float* __restrict__ n_wh,  const float* __restrict__ n_wsw,
    const float* __restrict__ n_wsb, const float* __restrict__ n_wv,
    const float* __restrict__ lnng,  const float* __restrict__ lnnb,
    const float* __restrict__ lneg,  const float* __restrict__ lneb,
    float* __restrict__ out)
{
    __shared__ __align__(16) char smraw[32768];   // padded: residency cap
    int bx = blockIdx.x;
    int tid = threadIdx.x, w = tid >> 5, l = tid & 31;

    if (bx >= NODE_BLOCKS) {
        // ================= EDGE PATH (fused sort + features + GVP + LN) ====
        int ebx = bx - NODE_BLOCKS;               // 0..2047
        float* feat = (float*)smraw;              // 8*32*8 = 2048 (16B aligned)
        float* xca  = feat + 2048;                // 192
        float* msk  = xca + 192;                  // 64
        int*   foc  = (int*)(msk + 64);           // 64
        int*   chs  = foc + 64;                   // 512
        float* Drow = (float*)(chs + 512);        // 4*64 (shared per row)
        int*   erow = (int*)(Drow + 256);         // 4*64

        int bt = ebx >> 4, sub = ebx & 15, b = bt >> 6;
        const float* Xbt = X + (size_t)bt * 768;
        for (int idx = tid; idx < 192; idx += 256)
            xca[idx] = Xbt[(idx / 3) * 12 + 3 + (idx % 3)];
        if (tid < 64) {
            msk[tid] = mask[bt * 64 + tid];
            foc[tid] = focus[bt * 64 + tid];
        }
        const int* chainB = chain + b * L;
        bool chsm = (L <= 512);
        if (chsm) for (int idx = tid; idx < L; idx += 256) chs[idx] = chainB[idx];
        __syncthreads();

        // ---- warp -> (row, half): r = w>>1, t2 = w&1; even warp sorts ----
        int r = w >> 1;
        int i = sub * 4 + r;
        int t2 = w & 1;
        float xix = xca[i * 3], xiy = xca[i * 3 + 1], xiz = xca[i * 3 + 2];
        float mi = msk[i];

        if (t2 == 0) {
            int j0 = l, j1 = l + 32;
            float d0, d1, a0_, a1_;
            {
                float dx = __fadd_rn(xca[j0 * 3],     -xix);
                float dy = __fadd_rn(xca[j0 * 3 + 1], -xiy);
                float dz = __fadd_rn(xca[j0 * 3 + 2], -xiz);
                float s = __fadd_rn(__fadd_rn(__fmul_rn(dx, dx), __fmul_rn(dy, dy)), __fmul_rn(dz, dz));
                d0 = __fmul_rn(__fmul_rn(msk[j0], mi), sqrtf(__fadd_rn(s, 1e-6f)));
                dx = __fadd_rn(xca[j1 * 3],     -xix);
                dy = __fadd_rn(xca[j1 * 3 + 1], -xiy);
                dz = __fadd_rn(xca[j1 * 3 + 2], -xiz);
                s = __fadd_rn(__fadd_rn(__fmul_rn(dx, dx), __fmul_rn(dy, dy)), __fmul_rn(dz, dz));
                d1 = __fmul_rn(__fmul_rn(msk[j1], mi), sqrtf(__fadd_rn(s, 1e-6f)));
            }
            float mx = fmaxf(d0, d1);
            #pragma unroll
            for (int o = 16; o; o >>= 1) mx = fmaxf(mx, __shfl_xor_sync(0xffffffffu, mx, o));
            float dmax = mx + 1.0f;
            {
                float m20 = __fmul_rn(msk[j0], mi);
                float m21 = __fmul_rn(msk[j1], mi);
                a0_ = __fadd_rn(d0, __fmul_rn(1.0f - m20, dmax));
                a1_ = __fadd_rn(d1, __fmul_rn(1.0f - m21, dmax));
            }
            Drow[r * 64 + j0] = a0_;
            Drow[r * 64 + j1] = a1_;
            __syncwarp();
            int r0 = 0, r1 = 0;
            #pragma unroll 16
            for (int k = 0; k < 64; k++) {
                float dk = Drow[r * 64 + k];
                r0 += (int)(dk < a0_) | ((int)(dk == a0_) & (int)(k < j0));
                r1 += (int)(dk < a1_) | ((int)(dk == a1_) & (int)(k < j1));
            }
            erow[r * 64 + r0] = j0;
            erow[r * 64 + r1] = j1;
        }
        __syncthreads();

        int nbr0 = erow[r * 64];
        int c0 = chsm ? chs[foc[nbr0]] : chainB[foc[nbr0]];
        size_t gebase = (size_t)bt * 4096 + (size_t)i * 64;
        float* frl = feat + w * 256 + l * 8;
        const float* fw = feat + w * 256;

        {
            // ---- phase 1 (no init dependency): feature row + offsets ----
            int e = t2 * 32 + l;
            int nbr = erow[r * 64 + e];
            float dn = Drow[r * 64 + nbr];
            int an = foc[nbr];
            size_t ge = gebase + e;
            out[OFF_EI + ge] = (float)nbr;
            out[OFF_AB + ge] = (float)an;

            float dx = xca[nbr * 3]     - xix;
            float dy = xca[nbr * 3 + 1] - xiy;
            float dz = xca[nbr * 3 + 2] - xiz;
            float n2 = dx * dx + dy * dy + dz * dz;
            float invn = 1.0f / fmaxf(sqrtf(n2), 1e-12f);

            int same = ((chsm ? chs[an] : chainB[an]) == c0);
            float s = (n2 == 0.0f) ? 1.0f : 0.0f;
            int ctrow = same ? (an - i + 63) : 600;
            float dn64 = fminf(dn * 64.0f, 2046.9f);
            int ia = (int)dn64;
            float fa = dn64 - (float)ia;
            {
                float4 v = {dx * invn, dy * invn, dz * invn, s};
                *reinterpret_cast<float4*>(frl) = v;
                float4 u = {__int_as_float(ctrow * 32), __int_as_float(ia * 32), fa, 0.0f};
                *reinterpret_cast<float4*>(frl + 4) = u;
            }
            __syncwarp();

            // wait for init tables — overlapped with everything above
            cudaGridDependencySynchronize();

            // per-lane constants (init outputs — must be after the sync)
            float baseC = g_base[l];
            float dCc   = g_dC[l];
            float whv   = g_whv[l];
            float lg = lneg[l], lb = lneb[l];

            // ---- phase 2: lane = channel, 2-edge interleaved, LN-centered ----
            float* po = out + (OFF_E + (gebase + (size_t)(t2 * 32)) * 128) + l;
            for (int t = 0; t < 32; t += 2) {
                const float4* p = (const float4*)(fw + t * 8);
                float4 A0 = p[0], B0 = p[1];
                float4 A1 = p[2], B1 = p[3];
                int co0 = __float_as_int(B0.x), ro0 = __float_as_int(B0.y);
                int co1 = __float_as_int(B1.x), ro1 = __float_as_int(B1.y);
                float ct0 = g_ctab[co0 + l];
                float ct1 = g_ctab[co1 + l];
                float r00 = g_rbft[ro0 + l], r01 = g_rbft[ro0 + 32 + l];
                float r10 = g_rbft[ro1 + l], r11 = g_rbft[ro1 + 32 + l];
                float dv0 = fmaf(B0.z, r01 - r00, r00 + ct0);
                float dv1 = fmaf(B1.z, r11 - r10, r10 + ct1);
                dv0 += fmaf(A0.w, dCc, baseC);
                dv1 += fmaf(A1.w, dCc, baseC);

                // single variance butterfly per edge (2-way interleaved)
                float q0 = dv0 * dv0, q1 = dv1 * dv1;
                #pragma unroll
                for (int o = 16; o; o >>= 1) {
                    q0 += __shfl_xor_sync(0xffffffffu, q0, o);
                    q1 += __shfl_xor_sync(0xffffffffu, q1, o);
                }
                float iv0 = rsqrtf(fmaf(q0, 1.0f / 32.0f, 1e-5f));
                float iv1 = rsqrtf(fmaf(q1, 1.0f / 32.0f, 1e-5f));
                float so0 = fmaf(dv0 * iv0, lg, lb);
                float so1 = fmaf(dv1 * iv1, lg, lb);

                po[0]   = A0.x * whv;
                po[32]  = A0.y * whv;
                po[64]  = A0.z * whv;
                po[96]  = so0;
                po[128] = A1.x * whv;
                po[160] = A1.y * whv;
                po[192] = A1.z * whv;
                po[224] = so1;
                po += 256;
            }
        }
    } else {
        // ========================= NODE PATH (no init dependency) ==========
        float* wsw  = (float*)smraw;          // 70*64
        float* whs  = wsw + 4480;             // 3*64
        float* whvs = whs + 192;              // 3*64
        float* wsb  = whvs + 192;             // 64
        float* glng = wsb + 64;               // 64
        float* glnb = glng + 64;              // 64
        float* sdi  = glnb + 64;              // 64*6
        float* vmat = sdi + 384;              // 64*9
        float* vnbuf = vmat + 576;            // 8*64 (16B aligned)

        int bt = bx;

        for (int idx = tid; idx < 4480; idx += 256) wsw[idx] = n_wsw[idx];
        for (int idx = tid; idx < 192; idx += 256)  whs[idx] = n_wh[idx];
        if (tid < 64) { wsb[tid] = n_wsb[tid]; glng[tid] = lnng[tid]; glnb[tid] = lnnb[tid]; }

        const float* Xbt = X + (size_t)bt * 768;
        if (tid < 192) {
            // dihedrals: one (i,t) per thread
            int i = tid / 3, t = tid - 3 * i;
            int r = 3 * i + t - 1;
            float ang = 0.0f;
            if (r >= 0 && r < 189) {
                float P[4][3];
                #pragma unroll
                for (int qq = 0; qq < 4; qq++) {
                    int p = r + qq;
                    const float* A = Xbt + (p / 3) * 12 + (p % 3) * 3;
                    P[qq][0] = A[0]; P[qq][1] = A[1]; P[qq][2] = A[2];
                }
                float u2x = P[1][0] - P[0][0], u2y = P[1][1] - P[0][1], u2z = P[1][2] - P[0][2];
                float u1x = P[2][0] - P[1][0], u1y = P[2][1] - P[1][1], u1z = P[2][2] - P[1][2];
                float u0x = P[3][0] - P[2][0], u0y = P[3][1] - P[2][1], u0z = P[3][2] - P[2][2];
                nrm3(u2x, u2y, u2z); nrm3(u1x, u1y, u1z); nrm3(u0x, u0y, u0z);
                float ax = u2y * u1z - u2z * u1y;
                float ay = u2z * u1x - u2x * u1z;
                float az = u2x * u1y - u2y * u1x; nrm3(ax, ay, az);
                float bx_ = u1y * u0z - u1z * u0y;
                float by_ = u1z * u0x - u1x * u0z;
                float bz_ = u1x * u0y - u1y * u0x; nrm3(bx_, by_, bz_);
                float cd = ax * bx_ + ay * by_ + az * bz_;
                cd = fminf(fmaxf(cd, -1.0f + 1e-7f), 1.0f - 1e-7f);
                float sg = u2x * bx_ + u2y * by_ + u2z * bz_;
                float sn = (sg > 0.f) ? 1.f : ((sg < 0.f) ? -1.f : 0.f);
                ang = sn * acosf(cd);
            }
            sdi[i * 6 + t]     = cosf(ang);
            sdi[i * 6 + 3 + t] = sinf(ang);
        } else {
            // frames: sidechain vec + fwd + bwd, one node per thread
            int i = tid - 192;
            const float* Xr = Xbt + (size_t)i * 12;
            float nx = Xr[0], ny = Xr[1], nz = Xr[2];
            float ox = Xr[3], oy = Xr[4], oz = Xr[5];
            float cx = Xr[6], cy = Xr[7], cz = Xr[8];
            float ccx = cx - ox, ccy = cy - oy, ccz = cz - oz; nrm3(ccx, ccy, ccz);
            float nnx = nx - ox, nny = ny - oy, nnz = nz - oz; nrm3(nnx, nny, nnz);
            float bxv = ccx + nnx, byv = ccy + nny, bzv = ccz + nnz; nrm3(bxv, byv, bzv);
            float px = ccy * nnz - ccz * nny;
            float py = ccz * nnx - ccx * nnz;
            float pz = ccx * nny - ccy * nnx; nrm3(px, py, pz);
            const float k1 = 0.57735026918962576f, k2 = 0.81649658092772603f;
            vmat[i * 9 + 0] = -bxv * k1 - px * k2;
            vmat[i * 9 + 3] = -byv * k1 - py * k2;
            vmat[i * 9 + 6] = -bzv * k1 - pz * k2;
            float fx = 0.f, fy = 0.f, fz = 0.f;
            if (i < 63) {
                const float* Xn2 = Xbt + (size_t)(i + 1) * 12 + 3;
                fx = Xn2[0] - ox; fy = Xn2[1] - oy; fz = Xn2[2] - oz; nrm3(fx, fy, fz);
            }
            vmat[i * 9 + 1] = fx; vmat[i * 9 + 4] = fy; vmat[i * 9 + 7] = fz;
            float gx = 0.f, gy = 0.f, gz = 0.f;
            if (i > 0) {
                const float* Xp = Xbt + (size_t)(i - 1) * 12 + 3;
                gx = ox - Xp[0]; gy = oy - Xp[1]; gz = oz - Xp[2]; nrm3(gx, gy, gz);
                gx = -gx; gy = -gy; gz = -gz;
            }
            vmat[i * 9 + 2] = gx; vmat[i * 9 + 5] = gy; vmat[i * 9 + 8] = gz;
        }
        __syncthreads();

        // whv = wh @ wv (3 x 64)
        for (int idx = tid; idx < 192; idx += 256) {
            int p = idx >> 6, h = idx & 63;
            float a = 0.f;
            for (int m = 0; m < 64; m++) a = fmaf(whs[p * 64 + m], n_wv[m * 64 + h], a);
            whvs[idx] = a;
        }
        __syncthreads();

        for (int nd = w; nd < 64; nd += 8) {
            float vm[9];
            #pragma unroll
            for (int z = 0; z < 9; z++) vm[z] = vmat[nd * 9 + z];
            int h0 = l, h1 = l + 32;
            float vh0[3], vh1[3];
            #pragma unroll
            for (int c = 0; c < 3; c++) {
                vh0[c] = vm[c * 3 + 0] * whs[0 * 64 + h0] + vm[c * 3 + 1] * whs[1 * 64 + h0] + vm[c * 3 + 2] * whs[2 * 64 + h0];
                vh1[c] = vm[c * 3 + 0] * whs[0 * 64 + h1] + vm[c * 3 + 1] * whs[1 * 64 + h1] + vm[c * 3 + 2] * whs[2 * 64 + h1];
            }
            float vn0 = sqrtf(vh0[0] * vh0[0] + vh0[1] * vh0[1] + vh0[2] * vh0[2] + 1e-8f);
            float vn1 = sqrtf(vh1[0] * vh1[0] + vh1[1] * vh1[1] + vh1[2] * vh1[2] + 1e-8f);
            vnbuf[w * 64 + l] = vn0;
            vnbuf[w * 64 + l + 32] = vn1;
            __syncwarp();

            float acc0 = wsb[h0], acc1 = wsb[h1];
            #pragma unroll
            for (int k = 0; k < 6; k++) {
                float dk = sdi[nd * 6 + k];
                acc0 = fmaf(dk, wsw[k * 64 + h0], acc0);
                acc1 = fmaf(dk, wsw[k * 64 + h1], acc1);
            }
            #pragma unroll
            for (int m = 0; m < 64; m += 4) {
                float4 v4 = *reinterpret_cast<const float4*>(&vnbuf[w * 64 + m]);
                acc0 = fmaf(v4.x, wsw[(6 + m) * 64 + h0], acc0);
                acc1 = fmaf(v4.x, wsw[(6 + m) * 64 + h1], acc1);
                acc0 = fmaf(v4.y, wsw[(7 + m) * 64 + h0], acc0);
                acc1 = fmaf(v4.y, wsw[(7 + m) * 64 + h1], acc1);
                acc0 = fmaf(v4.z, wsw[(8 + m) * 64 + h0], acc0);
                acc1 = fmaf(v4.z, wsw[(8 + m) * 64 + h1], acc1);
                acc0 = fmaf(v4.w, wsw[(9 + m) * 64 + h0], acc0);
                acc1 = fmaf(v4.w, wsw[(9 + m) * 64 + h1], acc1);
            }
            __syncwarp();

            // LayerNorm over 64 channels: 2 interleaved butterflies
            float ssum = acc0 + acc1;
            #pragma unroll
            for (int o = 16; o; o >>= 1) ssum += __shfl_xor_sync(0xffffffffu, ssum, o);
            float mean = ssum * (1.0f / 64.0f);
            float dv0 = acc0 - mean, dv1 = acc1 - mean;
            float vs = dv0 * dv0 + dv1 * dv1;
            #pragma unroll
            for (int o = 16; o; o >>= 1) vs += __shfl_xor_sync(0xffffffffu, vs, o);
            float inv = rsqrtf(vs * (1.0f / 64.0f) + 1e-5f);
            float o0 = dv0 * inv * glng[h0] + glnb[h0];
            float o1 = dv1 * inv * glng[h1] + glnb[h1];

            size_t vb = ((size_t)bt * 64 + nd) * 256;
            #pragma unroll
            for (int c = 0; c < 3; c++) {
                float vo0 = vm[c * 3 + 0] * whvs[0 * 64 + h0] + vm[c * 3 + 1] * whvs[1 * 64 + h0] + vm[c * 3 + 2] * whvs[2 * 64 + h0];
                float vo1 = vm[c * 3 + 0] * whvs[0 * 64 + h1] + vm[c * 3 + 1] * whvs[1 * 64 + h1] + vm[c * 3 + 2] * whvs[2 * 64 + h1];
                out[vb + c * 64 + h0] = vo0;
                out[vb + c * 64 + h1] = vo1;
            }
            out[vb + 192 + h0] = o0;
            out[vb + 192 + h1] = o1;
        }
    }
}

// ---------------------------------------------------------------------------
extern "C" void kernel_launch(void* const* d_in, const int* in_sizes, int n_in,
                              void* d_out, int out_size)
{
    const float* X      = (const float*)d_in[0];
    const float* mask   = (const float*)d_in[1];
    const int*   chain  = (const int*)d_in[2];
    const int*   focus  = (const int*)d_in[3];
    const float* n_wh   = (const float*)d_in[4];
    const float* n_wsw  = (const float*)d_in[5];
    const float* n_wsb  = (const float*)d_in[6];
    const float* n_wv   = (const float*)d_in[7];
    const float* e_wh   = (const float*)d_in[8];
    const float* e_wsw  = (const float*)d_in[9];
    const float* e_wsb  = (const float*)d_in[10];
    const float* e_wv   = (const float*)d_in[11];
    const float* ln_n_g = (const float*)d_in[12];
    const float* ln_n_b = (const float*)d_in[13];
    const float* ln_e_g = (const float*)d_in[14];
    const float* ln_e_b = (const float*)d_in[15];
    float* out = (float*)d_out;
    int L = in_sizes[2] / 2;

    init_all_kernel<<<387, 256>>>(e_wh, e_wsw, e_wsb, e_wv);

    // PDL secondary: launch mega so its pre-table work overlaps init.
    cudaLaunchConfig_t cfg = {};
    cfg.gridDim = dim3(NODE_BLOCKS + EDGE_BLOCKS, 1, 1);
    cfg.blockDim = dim3(256, 1, 1);
    cfg.dynamicSmemBytes = 0;
    cfg.stream = 0;
    cudaLaunchAttribute attrs[1];
    attrs[0].id = cudaLaunchAttributeProgrammaticStreamSerialization;
    attrs[0].val.programmaticStreamSerializationAllowed = 1;
    cfg.attrs = attrs;
    cfg.numAttrs = 1;
    cudaLaunchKernelEx(&cfg, mega_kernel,
        X, mask, chain, focus, L,
        n_wh, n_wsw, n_wsb, n_wv,
        ln_n_g, ln_n_b, ln_e_g, ln_e_b, out);
}